// round 5
// baseline (speedup 1.0000x reference)
#include <cuda_runtime.h>
#include <math.h>
#include <float.h>
#include <stdint.h>

#define D        512
#define NTYPES   26
#define NPER     128
#define NCODES   (NTYPES * NPER)
#define MAXN     32768
#define MAXS     1024
#define TEMP     0.07f
#define EPSN     1e-12f
#define MAXTILES 16
#define HB       256            // histogram rows of 128 tokens (MAXN/128)
#define WROW     12             // smem words per row: 8 data + 4 pad (conflict-free)
#define STW      (128 * WROW)   // words per stage array
#define MARGIN   6e-3f          // bf16-score rescore margin (~43 sigma)

// ---------------- scratch ----------------
__device__ float    g_se[(size_t)MAXS * D];
__device__ float    g_esq[NCODES];
__device__ uint32_t g_ehi[(size_t)NCODES * 256];   // packed bf16 hi, [code][word]
__device__ int      g_hist[HB][NTYPES];
__device__ int      g_off[NTYPES + 1];
__device__ int      g_order[MAXN];
__device__ float    g_loss;
__device__ float    g_usum;
__device__ int      g_done;

// ---------------- helpers ----------------
__device__ __forceinline__ uint32_t bfpack(float lo, float hi) {
    uint32_t r;
    asm("cvt.rn.bf16x2.f32 %0, %1, %2;" : "=r"(r) : "f"(hi), "f"(lo));
    return r;
}

__device__ __forceinline__ void mma_bf16(float* c, const uint32_t* a, const uint32_t* b) {
    asm volatile(
        "mma.sync.aligned.m16n8k16.row.col.f32.bf16.bf16.f32 "
        "{%0,%1,%2,%3}, {%4,%5,%6,%7}, {%8,%9}, {%0,%1,%2,%3};"
        : "+f"(c[0]), "+f"(c[1]), "+f"(c[2]), "+f"(c[3])
        : "r"(a[0]), "r"(a[1]), "r"(a[2]), "r"(a[3]),
          "r"(b[0]), "r"(b[1]));
}

__device__ __forceinline__ void ldm_x4(uint32_t* r, uint32_t saddr) {
    asm volatile("ldmatrix.sync.aligned.m8n8.x4.shared.b16 {%0,%1,%2,%3}, [%4];"
                 : "=r"(r[0]), "=r"(r[1]), "=r"(r[2]), "=r"(r[3]) : "r"(saddr));
}

// ---------------- prep: init + esq + E bf16 hi + histogram + se-normalize -----
__global__ __launch_bounds__(128) void k_prep(const float* __restrict__ emb,
                                              const int* __restrict__ Q, int N,
                                              const int* __restrict__ sampled, int S) {
    int b = blockIdx.x;
    if (b < NCODES) {
        if (b == 0 && threadIdx.x == 0) { g_loss = 0.f; g_usum = 0.f; }
        const float4* er = (const float4*)(emb + (size_t)b * D);
        float4 a = er[threadIdx.x];
        uint32_t h0 = bfpack(a.x, a.y);
        uint32_t h1 = bfpack(a.z, a.w);
        size_t base = (size_t)b * 256 + threadIdx.x * 2;
        *(uint2*)&g_ehi[base] = make_uint2(h0, h1);
        float ss = a.x*a.x + a.y*a.y + a.z*a.z + a.w*a.w;
        #pragma unroll
        for (int o = 16; o > 0; o >>= 1) ss += __shfl_down_sync(0xffffffffu, ss, o);
        __shared__ float ws[4];
        if ((threadIdx.x & 31) == 0) ws[threadIdx.x >> 5] = ss;
        __syncthreads();
        if (threadIdx.x == 0) g_esq[b] = ws[0] + ws[1] + ws[2] + ws[3];
    } else if (b < NCODES + HB) {
        int h = b - NCODES;
        __shared__ int cnt[NTYPES];
        if (threadIdx.x < NTYPES) cnt[threadIdx.x] = 0;
        __syncthreads();
        int i = h * 128 + threadIdx.x;
        if (i < N) atomicAdd(&cnt[Q[i]], 1);
        __syncthreads();
        if (threadIdx.x < NTYPES) g_hist[h][threadIdx.x] = cnt[threadIdx.x];
    } else {
        int s = b - NCODES - HB;            // 0..S-1 : normalize sampled row
        int row = sampled[s];
        float4 a = ((const float4*)(emb + (size_t)row * D))[threadIdx.x];
        float ss = a.x*a.x + a.y*a.y + a.z*a.z + a.w*a.w;
        #pragma unroll
        for (int o = 16; o > 0; o >>= 1) ss += __shfl_down_sync(0xffffffffu, ss, o);
        __shared__ float ws2[4];
        if ((threadIdx.x & 31) == 0) ws2[threadIdx.x >> 5] = ss;
        __syncthreads();
        float tot = ws2[0] + ws2[1] + ws2[2] + ws2[3];
        float inv = 1.0f / fmaxf(sqrtf(tot), EPSN);
        ((float4*)(g_se + (size_t)s * D))[threadIdx.x] =
            make_float4(a.x*inv, a.y*inv, a.z*inv, a.w*inv);
    }
}

// ---------------- scatter (deterministic; block 0 publishes g_off) ------------
__global__ __launch_bounds__(256) void k_scatter(const int* __restrict__ Q, int N) {
    __shared__ int stot[NTYPES], spre[NTYPES], soff[NTYPES + 1], sbase[NTYPES];
    __shared__ int wcnt[8][NTYPES];
    int b = blockIdx.x;
    int tid = threadIdx.x;
    int lane = tid & 31, wid = tid >> 5;

    if (tid < NTYPES) {
        int tot = 0, pre = 0, lim = 2 * b;
        #pragma unroll 8
        for (int r = 0; r < HB; r++) {
            int v = g_hist[r][tid];
            tot += v;
            if (r < lim) pre += v;
        }
        stot[tid] = tot; spre[tid] = pre;
    }
    if (tid < 8 * NTYPES) wcnt[tid / NTYPES][tid % NTYPES] = 0;
    __syncthreads();
    if (tid == 0) {
        int acc = 0;
        #pragma unroll
        for (int t = 0; t < NTYPES; t++) { soff[t] = acc; acc += stot[t]; }
        soff[NTYPES] = acc;
    }
    __syncthreads();
    if (tid < NTYPES) sbase[tid] = soff[tid] + spre[tid];
    if (b == 0 && tid < NTYPES + 1) g_off[tid] = soff[tid];

    int i = b * 256 + tid;
    int ty = (i < N) ? Q[i] : -1;
    unsigned mask = __match_any_sync(0xffffffffu, ty);
    int rinw = __popc(mask & ((1u << lane) - 1u));
    int lead = __ffs(mask) - 1;
    if (lane == lead && ty >= 0) wcnt[wid][ty] = __popc(mask);
    __syncthreads();
    if (ty >= 0) {
        int rank = rinw;
        #pragma unroll
        for (int w = 0; w < 8; w++) if (w < wid) rank += wcnt[w][ty];
        g_order[sbase[ty] + rank] = i;
    }
}

// ---------------- hi-only bf16 GEMM + argmin + fp32 rescore + quant + loss ----
extern __shared__ uint32_t dynsm[];
// layout: [XH0, XH1, EH0, EH1], each STW words (24 KB total)
__global__ __launch_bounds__(256, 2) void k_gemm_fused(const float* __restrict__ x,
                                                       const float* __restrict__ emb,
                                                       float* __restrict__ out,
                                                       float* __restrict__ out_idx) {
    int t = blockIdx.y;
    int start = g_off[t], end = g_off[t + 1];
    int tile0 = start + blockIdx.x * 128;
    if (tile0 >= end) return;
    int rows = min(128, end - tile0);

    __shared__ int   toks[128];
    __shared__ float sEsq[128];
    __shared__ float sRow[128][2];
    __shared__ float sInv[128], sN2[128];
    __shared__ float sval[2][128];
    __shared__ int   sidx[2][128];
    __shared__ int   scol[128];
    __shared__ float sSc[128];
    __shared__ int   cand_cnt[128];
    __shared__ int   cand_col[128][7];
    __shared__ float lsum[4];

    int tid = threadIdx.x, lane = tid & 31, wid = tid >> 5;
    int g = lane >> 2, tig = lane & 3;
    int m0 = (wid & 3) * 32;
    int nw = wid >> 2;
    int n0 = nw * 64;

    if (tid < 128) {
        toks[tid] = g_order[tile0 + min(tid, rows - 1)];
        sEsq[tid] = g_esq[t * NPER + tid];
        cand_cnt[tid] = 0;
    }
    __syncthreads();

    int lm = tid >> 1, half = tid & 1;
    const float4*   xr = (const float4*)(x + (size_t)toks[lm] * D) + half * 2;
    const uint32_t* eH = g_ehi + (size_t)(t * NPER + lm) * 256 + half * 4;

    uint32_t smb = (uint32_t)__cvta_generic_to_shared(dynsm);
    int arow = m0 + (lane & 8) + (lane & 7);
    uint32_t aoff = (uint32_t)((arow * WROW + ((lane & 16) >> 2)) * 4);
    int brow = n0 + ((lane >> 4) & 1) * 8 + (lane & 7);
    uint32_t boff = (uint32_t)((brow * WROW + ((lane >> 3) & 1) * 4) * 4);

    float acc[2][8][4];
    #pragma unroll
    for (int s = 0; s < 2; s++)
        #pragma unroll
        for (int j = 0; j < 8; j++)
            #pragma unroll
            for (int c = 0; c < 4; c++) acc[s][j][c] = 0.f;
    float rowsq = 0.f;

    float4 px0 = xr[0], px1 = xr[1];
    uint4  peH = *(const uint4*)eH;

    // stage 0 fill
    {
        float vx[8] = {px0.x,px0.y,px0.z,px0.w,px1.x,px1.y,px1.z,px1.w};
        uint32_t xh[4];
        #pragma unroll
        for (int w = 0; w < 4; w++) {
            float a0 = vx[2*w], a1 = vx[2*w+1];
            xh[w] = bfpack(a0, a1);
            rowsq += a0*a0 + a1*a1;
        }
        int so = lm * WROW + half * 4;
        *(uint4*)(dynsm + 0*STW + so) = make_uint4(xh[0],xh[1],xh[2],xh[3]);
        *(uint4*)(dynsm + 2*STW + so) = peH;
    }
    __syncthreads();

    for (int c = 0; c < 32; c++) {
        int cur = c & 1, nxt = cur ^ 1;
        if (c < 31) {
            px0 = xr[(c+1)*4]; px1 = xr[(c+1)*4 + 1];
            peH = *(const uint4*)(eH + (c+1)*8);
        }
        uint32_t baseA = smb + (uint32_t)(0 + cur) * (STW * 4);
        uint32_t baseE = smb + (uint32_t)(2 + cur) * (STW * 4);

        uint32_t aH[2][4];
        #pragma unroll
        for (int s = 0; s < 2; s++)
            ldm_x4(aH[s], baseA + aoff + s * (16 * WROW * 4));
        #pragma unroll
        for (int jj = 0; jj < 4; jj++) {
            uint32_t bh[4];
            ldm_x4(bh, baseE + boff + jj * (16 * WROW * 4));
            #pragma unroll
            for (int jh = 0; jh < 2; jh++) {
                int j = jj * 2 + jh;
                uint32_t bH[2] = { bh[2*jh], bh[2*jh+1] };
                mma_bf16(acc[0][j], aH[0], bH);
                mma_bf16(acc[1][j], aH[1], bH);
            }
        }
        if (c < 31) {
            float vx[8] = {px0.x,px0.y,px0.z,px0.w,px1.x,px1.y,px1.z,px1.w};
            uint32_t xh[4];
            #pragma unroll
            for (int w = 0; w < 4; w++) {
                float a0 = vx[2*w], a1 = vx[2*w+1];
                xh[w] = bfpack(a0, a1);
                rowsq += a0*a0 + a1*a1;
            }
            int so = lm * WROW + half * 4;
            *(uint4*)(dynsm + (0+nxt)*STW + so) = make_uint4(xh[0],xh[1],xh[2],xh[3]);
            *(uint4*)(dynsm + (2+nxt)*STW + so) = peH;
        }
        __syncthreads();
    }

    // per-row ||x||^2 -> inv_x
    sRow[lm][half] = rowsq;
    __syncthreads();
    if (tid < 128) {
        float n2 = sRow[tid][0] + sRow[tid][1];
        sN2[tid]  = n2;
        sInv[tid] = 1.0f / fmaxf(sqrtf(n2), EPSN);
    }
    __syncthreads();

    // argmin pass 1: score = esq - 2*inv_x*dot (bf16-approx)
    #pragma unroll
    for (int s = 0; s < 2; s++) {
        #pragma unroll
        for (int rh = 0; rh < 2; rh++) {
            int row = m0 + s*16 + g + rh*8;
            float inv2 = 2.0f * sInv[row];
            float bv = FLT_MAX;
            int   bi = 1 << 30;
            #pragma unroll
            for (int j = 0; j < 8; j++) {
                #pragma unroll
                for (int cc = 0; cc < 2; cc++) {
                    int col = n0 + 8*j + 2*tig + cc;
                    float sc = fmaf(-inv2, acc[s][j][rh*2 + cc], sEsq[col]);
                    if (sc < bv || (sc == bv && col < bi)) { bv = sc; bi = col; }
                }
            }
            #pragma unroll
            for (int o = 2; o > 0; o >>= 1) {
                float ov = __shfl_down_sync(0xffffffffu, bv, o, 4);
                int   oi = __shfl_down_sync(0xffffffffu, bi, o, 4);
                if (ov < bv || (ov == bv && oi < bi)) { bv = ov; bi = oi; }
            }
            if (tig == 0) { sval[nw][row] = bv; sidx[nw][row] = bi; }
        }
    }
    __syncthreads();

    if (tid < 128) {
        float v0 = sval[0][tid], v1 = sval[1][tid];
        int   i0 = sidx[0][tid], i1 = sidx[1][tid];
        if (v1 < v0 || (v1 == v0 && i1 < i0)) { scol[tid] = i1; sSc[tid] = v1; }
        else                                  { scol[tid] = i0; sSc[tid] = v0; }
    }
    __syncthreads();

    // pass 2: collect candidates within MARGIN of row-min
    #pragma unroll
    for (int s = 0; s < 2; s++) {
        #pragma unroll
        for (int rh = 0; rh < 2; rh++) {
            int row = m0 + s*16 + g + rh*8;
            float inv2 = 2.0f * sInv[row];
            float thresh = sSc[row] + MARGIN;
            int   win = scol[row];
            #pragma unroll
            for (int j = 0; j < 8; j++) {
                #pragma unroll
                for (int cc = 0; cc < 2; cc++) {
                    int col = n0 + 8*j + 2*tig + cc;
                    float sc = fmaf(-inv2, acc[s][j][rh*2 + cc], sEsq[col]);
                    if (sc <= thresh && col != win) {
                        int p = atomicAdd(&cand_cnt[row], 1);
                        if (p < 7) cand_col[row][p] = col;
                    }
                }
            }
        }
    }
    __syncthreads();

    // rescore close rows exactly in fp32 (warp per row)
    const float* ebase = emb + (size_t)t * NPER * D;
    for (int r = wid; r < rows; r += 8) {
        int nc = cand_cnt[r];
        if (nc == 0) continue;
        int tok = toks[r];
        const float4* xp = (const float4*)(x + (size_t)tok * D);
        float4 xa = xp[lane], xb = xp[lane + 32], xc = xp[lane + 64], xd = xp[lane + 96];
        float inv2 = 2.0f * sInv[r];
        float bv = FLT_MAX;
        int   bi = 1 << 30;
        int total = (nc > 7) ? NPER : (nc + 1);
        for (int q = 0; q < total; q++) {
            int col;
            if (nc > 7) col = q;
            else        col = (q == 0) ? scol[r] : cand_col[r][q - 1];
            const float4* ep = (const float4*)(ebase + (size_t)col * D);
            float4 ea = ep[lane], eb = ep[lane + 32], ec = ep[lane + 64], ed = ep[lane + 96];
            float d = xa.x*ea.x + xa.y*ea.y + xa.z*ea.z + xa.w*ea.w
                    + xb.x*eb.x + xb.y*eb.y + xb.z*eb.z + xb.w*eb.w
                    + xc.x*ec.x + xc.y*ec.y + xc.z*ec.z + xc.w*ec.w
                    + xd.x*ed.x + xd.y*ed.y + xd.z*ed.z + xd.w*ed.w;
            #pragma unroll
            for (int o = 16; o > 0; o >>= 1) d += __shfl_xor_sync(0xffffffffu, d, o);
            float sc = fmaf(-inv2, d, sEsq[col]);
            if (sc < bv || (sc == bv && col < bi)) { bv = sc; bi = col; }
        }
        if (lane == 0) { scol[r] = bi; sSc[r] = bv; }
    }
    __syncthreads();

    // idx write + analytic loss
    float lacc = 0.f;
    if (tid < 128 && tid < rows) {
        int col = scol[tid];
        out_idx[toks[tid]] = (float)(t * NPER + col);
        float esqw = sEsq[col];
        float inve = 1.0f / fmaxf(sqrtf(esqw), EPSN);
        lacc = esqw*inve*inve + sN2[tid]*sInv[tid]*sInv[tid] - (esqw - sSc[tid])*inve;
    }
    #pragma unroll
    for (int o = 16; o > 0; o >>= 1) lacc += __shfl_down_sync(0xffffffffu, lacc, o);
    if (tid < 128 && lane == 0) lsum[wid] = lacc;
    __syncthreads();
    if (tid == 0)
        atomicAdd(&g_loss, lsum[0] + lsum[1] + lsum[2] + lsum[3]);

    // write quantized rows (straight-through forward value == normalized code)
    for (int r = wid; r < rows; r += 8) {
        int tok = toks[r];
        int col = scol[r];
        float inve = 1.0f / fmaxf(sqrtf(sEsq[col]), EPSN);
        const float4* ep = (const float4*)(ebase + (size_t)col * D);
        float4* op = (float4*)(out + (size_t)tok * D);
        #pragma unroll
        for (int q = 0; q < 4; q++) {
            float4 e = ep[lane + q*32];
            op[lane + q*32] = make_float4(e.x*inve, e.y*inve, e.z*inve, e.w*inve);
        }
    }
}

// ---------------- uniform loss: 8 rows per block + finalize ----------------
__global__ __launch_bounds__(256) void k_usim(const int* __restrict__ sampled, int S,
                                              float* __restrict__ out, int N) {
    int i0 = blockIdx.x * 8;
    int R = min(8, S - i0);
    __shared__ float si[8][D];
    __shared__ int   slab[8];
    __shared__ float wsum[8][8], wpos[8][8];

    int tid = threadIdx.x, lane = tid & 31, wid = tid >> 5;
    for (int r = 0; r < R; r++) {
        ((float2*)si[r])[tid] = ((const float2*)(g_se + (size_t)(i0 + r) * D))[tid];
    }
    if (tid < R) slab[tid] = sampled[i0 + tid] / NPER;
    __syncthreads();

    float sum[8], pos[8];
    #pragma unroll
    for (int r = 0; r < 8; r++) { sum[r] = 0.f; pos[r] = 0.f; }

    for (int j = wid; j < S; j += 8) {
        const float4* gj = (const float4*)(g_se + (size_t)j * D);
        float4 a0 = gj[lane], a1 = gj[lane + 32], a2 = gj[lane + 64], a3 = gj[lane + 96];
        int labj = sampled[j] / NPER;
        #pragma unroll
        for (int r = 0; r < 8; r++) {
            if (r >= R) break;
            const float4* bj = (const float4*)si[r];
            float4 b0 = bj[lane], b1 = bj[lane + 32], b2 = bj[lane + 64], b3 = bj[lane + 96];
            float d = a0.x*b0.x + a0.y*b0.y + a0.z*b0.z + a0.w*b0.w
                    + a1.x*b1.x + a1.y*b1.y + a1.z*b1.z + a1.w*b1.w
                    + a2.x*b2.x + a2.y*b2.y + a2.z*b2.z + a2.w*b2.w
                    + a3.x*b3.x + a3.y*b3.y + a3.z*b3.z + a3.w*b3.w;
            #pragma unroll
            for (int o = 16; o > 0; o >>= 1) d += __shfl_down_sync(0xffffffffu, d, o);
            if (lane == 0 && j != i0 + r) {
                float e = expf(d / TEMP);
                sum[r] += e;
                if (labj == slab[r]) pos[r] += e;
            }
        }
    }
    if (lane == 0) {
        #pragma unroll
        for (int r = 0; r < 8; r++) { wsum[wid][r] = sum[r]; wpos[wid][r] = pos[r]; }
    }
    __syncthreads();
    if (tid < R) {
        float ts = 0.f, tp = 0.f;
        #pragma unroll
        for (int w = 0; w < 8; w++) { ts += wsum[w][tid]; tp += wpos[w][tid]; }
        atomicAdd(&g_usum, -logf(tp / ts));
    }
    __threadfence();
    __syncthreads();
    if (tid == 0) {
        int old = atomicAdd(&g_done, 1);
        if (old == gridDim.x - 1) {
            g_done = 0;
            size_t ND = (size_t)N * D;
            out[ND]     = 1.25f * g_loss / (float)((size_t)N * D);
            out[ND + 1] = g_usum / (float)S;
        }
    }
}

// ---------------- launcher ----------------
extern "C" void kernel_launch(void* const* d_in, const int* in_sizes, int n_in,
                              void* d_out, int out_size) {
    const float* x       = (const float*)d_in[0];
    const int*   Q       = (const int*)d_in[1];
    const float* emb     = (const float*)d_in[2];
    const int*   sampled = (const int*)d_in[3];
    float* out = (float*)d_out;

    int N = in_sizes[0] / D;
    int S = in_sizes[3];
    size_t ND = (size_t)N * D;
    float* out_idx = out + ND + 2;

    cudaFuncSetAttribute(k_gemm_fused, cudaFuncAttributeMaxDynamicSharedMemorySize,
                         4 * STW * 4);

    k_prep<<<NCODES + HB + S, 128>>>(emb, Q, N, sampled, S);
    k_scatter<<<(N + 255) / 256, 256>>>(Q, N);
    dim3 gg(MAXTILES, NTYPES);
    k_gemm_fused<<<gg, 256, 4 * STW * 4>>>(x, emb, out, out_idx);
    k_usim<<<(S + 7) / 8, 256>>>(sampled, S, out, N);
}

// round 6
// speedup vs baseline: 1.5288x; 1.5288x over previous
#include <cuda_runtime.h>
#include <math.h>
#include <float.h>
#include <stdint.h>

#define D        512
#define NTYPES   26
#define NPER     128
#define NCODES   (NTYPES * NPER)
#define MAXN     32768
#define MAXS     1024
#define TEMP     0.07f
#define EPSN     1e-12f
#define MAXTILES 16
#define HB       256            // histogram rows of 128 tokens (MAXN/128)
#define WROW     12             // smem words per row: 8 data + 4 pad (conflict-free)
#define STW      (128 * WROW)   // words per stage array
#define MARGIN   6e-3f          // bf16-score rescore margin (~43 sigma)

// ---------------- scratch ----------------
__device__ float    g_se[(size_t)MAXS * D];
__device__ float    g_esq[NCODES];
__device__ uint32_t g_ehi[(size_t)NCODES * 256];   // packed bf16 hi, [code][word]
__device__ int      g_hist[HB][NTYPES];
__device__ int      g_off[NTYPES + 1];
__device__ int      g_order[MAXN];
__device__ float    g_loss;
__device__ float    g_usum;
__device__ int      g_done;

// ---------------- helpers ----------------
__device__ __forceinline__ uint32_t bfpack(float lo, float hi) {
    uint32_t r;
    asm("cvt.rn.bf16x2.f32 %0, %1, %2;" : "=r"(r) : "f"(hi), "f"(lo));
    return r;
}

__device__ __forceinline__ void mma_bf16(float* c, const uint32_t* a, const uint32_t* b) {
    asm volatile(
        "mma.sync.aligned.m16n8k16.row.col.f32.bf16.bf16.f32 "
        "{%0,%1,%2,%3}, {%4,%5,%6,%7}, {%8,%9}, {%0,%1,%2,%3};"
        : "+f"(c[0]), "+f"(c[1]), "+f"(c[2]), "+f"(c[3])
        : "r"(a[0]), "r"(a[1]), "r"(a[2]), "r"(a[3]),
          "r"(b[0]), "r"(b[1]));
}

__device__ __forceinline__ void ldm_x4(uint32_t* r, uint32_t saddr) {
    asm volatile("ldmatrix.sync.aligned.m8n8.x4.shared.b16 {%0,%1,%2,%3}, [%4];"
                 : "=r"(r[0]), "=r"(r[1]), "=r"(r[2]), "=r"(r[3]) : "r"(saddr));
}

// ---------------- prep: init + esq + E bf16 hi + histogram + se-normalize -----
__global__ __launch_bounds__(128) void k_prep(const float* __restrict__ emb,
                                              const int* __restrict__ Q, int N,
                                              const int* __restrict__ sampled, int S) {
    int b = blockIdx.x;
    if (b < NCODES) {
        if (b == 0 && threadIdx.x == 0) { g_loss = 0.f; g_usum = 0.f; }
        const float4* er = (const float4*)(emb + (size_t)b * D);
        float4 a = er[threadIdx.x];
        uint32_t h0 = bfpack(a.x, a.y);
        uint32_t h1 = bfpack(a.z, a.w);
        size_t base = (size_t)b * 256 + threadIdx.x * 2;
        *(uint2*)&g_ehi[base] = make_uint2(h0, h1);
        float ss = a.x*a.x + a.y*a.y + a.z*a.z + a.w*a.w;
        #pragma unroll
        for (int o = 16; o > 0; o >>= 1) ss += __shfl_down_sync(0xffffffffu, ss, o);
        __shared__ float ws[4];
        if ((threadIdx.x & 31) == 0) ws[threadIdx.x >> 5] = ss;
        __syncthreads();
        if (threadIdx.x == 0) g_esq[b] = ws[0] + ws[1] + ws[2] + ws[3];
    } else if (b < NCODES + HB) {
        int h = b - NCODES;
        __shared__ int cnt[NTYPES];
        if (threadIdx.x < NTYPES) cnt[threadIdx.x] = 0;
        __syncthreads();
        int i = h * 128 + threadIdx.x;
        if (i < N) atomicAdd(&cnt[Q[i]], 1);
        __syncthreads();
        if (threadIdx.x < NTYPES) g_hist[h][threadIdx.x] = cnt[threadIdx.x];
    } else {
        int s = b - NCODES - HB;            // 0..S-1 : normalize sampled row
        int row = sampled[s];
        float4 a = ((const float4*)(emb + (size_t)row * D))[threadIdx.x];
        float ss = a.x*a.x + a.y*a.y + a.z*a.z + a.w*a.w;
        #pragma unroll
        for (int o = 16; o > 0; o >>= 1) ss += __shfl_down_sync(0xffffffffu, ss, o);
        __shared__ float ws2[4];
        if ((threadIdx.x & 31) == 0) ws2[threadIdx.x >> 5] = ss;
        __syncthreads();
        float tot = ws2[0] + ws2[1] + ws2[2] + ws2[3];
        float inv = 1.0f / fmaxf(sqrtf(tot), EPSN);
        ((float4*)(g_se + (size_t)s * D))[threadIdx.x] =
            make_float4(a.x*inv, a.y*inv, a.z*inv, a.w*inv);
    }
}

// ---------------- scatter (deterministic; block 0 publishes g_off) ------------
__global__ __launch_bounds__(256) void k_scatter(const int* __restrict__ Q, int N) {
    __shared__ int stot[NTYPES], spre[NTYPES], soff[NTYPES + 1], sbase[NTYPES];
    __shared__ int wcnt[8][NTYPES];
    int b = blockIdx.x;
    int tid = threadIdx.x;
    int lane = tid & 31, wid = tid >> 5;

    if (tid < NTYPES) {
        int tot = 0, pre = 0, lim = 2 * b;
        #pragma unroll 8
        for (int r = 0; r < HB; r++) {
            int v = g_hist[r][tid];
            tot += v;
            if (r < lim) pre += v;
        }
        stot[tid] = tot; spre[tid] = pre;
    }
    if (tid < 8 * NTYPES) wcnt[tid / NTYPES][tid % NTYPES] = 0;
    __syncthreads();
    if (tid == 0) {
        int acc = 0;
        #pragma unroll
        for (int t = 0; t < NTYPES; t++) { soff[t] = acc; acc += stot[t]; }
        soff[NTYPES] = acc;
    }
    __syncthreads();
    if (tid < NTYPES) sbase[tid] = soff[tid] + spre[tid];
    if (b == 0 && tid < NTYPES + 1) g_off[tid] = soff[tid];

    int i = b * 256 + tid;
    int ty = (i < N) ? Q[i] : -1;
    unsigned mask = __match_any_sync(0xffffffffu, ty);
    int rinw = __popc(mask & ((1u << lane) - 1u));
    int lead = __ffs(mask) - 1;
    if (lane == lead && ty >= 0) wcnt[wid][ty] = __popc(mask);
    __syncthreads();
    if (ty >= 0) {
        int rank = rinw;
        #pragma unroll
        for (int w = 0; w < 8; w++) if (w < wid) rank += wcnt[w][ty];
        g_order[sbase[ty] + rank] = i;
    }
}

// ---------------- hi-only bf16 GEMM + argmin + fp32 rescore + quant + loss ----
extern __shared__ uint32_t dynsm[];
// layout: [XH0, XH1, EH0, EH1], each STW words (24 KB total)
__global__ __launch_bounds__(256, 2) void k_gemm_fused(const float* __restrict__ x,
                                                       const float* __restrict__ emb,
                                                       float* __restrict__ out,
                                                       float* __restrict__ out_idx) {
    int t = blockIdx.y;
    int start = g_off[t], end = g_off[t + 1];
    int tile0 = start + blockIdx.x * 128;
    if (tile0 >= end) return;
    int rows = min(128, end - tile0);

    __shared__ int   toks[128];
    __shared__ float sEsq[128];
    __shared__ float sRow[128][2];
    __shared__ float sInv[128], sN2[128];
    __shared__ float sval[2][128];
    __shared__ int   sidx[2][128];
    __shared__ int   scol[128];
    __shared__ float sSc[128];
    __shared__ int   cand_cnt[128];
    __shared__ int   cand_col[128][7];
    __shared__ float lsum[4];

    int tid = threadIdx.x, lane = tid & 31, wid = tid >> 5;
    int g = lane >> 2, tig = lane & 3;
    int m0 = (wid & 3) * 32;
    int nw = wid >> 2;
    int n0 = nw * 64;

    if (tid < 128) {
        toks[tid] = g_order[tile0 + min(tid, rows - 1)];
        sEsq[tid] = g_esq[t * NPER + tid];
        cand_cnt[tid] = 0;
    }
    __syncthreads();

    int lm = tid >> 1, half = tid & 1;
    const float4*   xr = (const float4*)(x + (size_t)toks[lm] * D) + half * 2;
    const uint32_t* eH = g_ehi + (size_t)(t * NPER + lm) * 256 + half * 4;

    uint32_t smb = (uint32_t)__cvta_generic_to_shared(dynsm);
    int arow = m0 + (lane & 8) + (lane & 7);
    uint32_t aoff = (uint32_t)((arow * WROW + ((lane & 16) >> 2)) * 4);
    int brow = n0 + ((lane >> 4) & 1) * 8 + (lane & 7);
    uint32_t boff = (uint32_t)((brow * WROW + ((lane >> 3) & 1) * 4) * 4);

    float acc[2][8][4];
    #pragma unroll
    for (int s = 0; s < 2; s++)
        #pragma unroll
        for (int j = 0; j < 8; j++)
            #pragma unroll
            for (int c = 0; c < 4; c++) acc[s][j][c] = 0.f;
    float rowsq = 0.f;

    float4 px0 = xr[0], px1 = xr[1];
    uint4  peH = *(const uint4*)eH;

    // stage 0 fill
    {
        float vx[8] = {px0.x,px0.y,px0.z,px0.w,px1.x,px1.y,px1.z,px1.w};
        uint32_t xh[4];
        #pragma unroll
        for (int w = 0; w < 4; w++) {
            float a0 = vx[2*w], a1 = vx[2*w+1];
            xh[w] = bfpack(a0, a1);
            rowsq += a0*a0 + a1*a1;
        }
        int so = lm * WROW + half * 4;
        *(uint4*)(dynsm + 0*STW + so) = make_uint4(xh[0],xh[1],xh[2],xh[3]);
        *(uint4*)(dynsm + 2*STW + so) = peH;
    }
    __syncthreads();

    for (int c = 0; c < 32; c++) {
        int cur = c & 1, nxt = cur ^ 1;
        if (c < 31) {
            px0 = xr[(c+1)*4]; px1 = xr[(c+1)*4 + 1];
            peH = *(const uint4*)(eH + (c+1)*8);
        }
        uint32_t baseA = smb + (uint32_t)(0 + cur) * (STW * 4);
        uint32_t baseE = smb + (uint32_t)(2 + cur) * (STW * 4);

        uint32_t aH[2][4];
        #pragma unroll
        for (int s = 0; s < 2; s++)
            ldm_x4(aH[s], baseA + aoff + s * (16 * WROW * 4));
        #pragma unroll
        for (int jj = 0; jj < 4; jj++) {
            uint32_t bh[4];
            ldm_x4(bh, baseE + boff + jj * (16 * WROW * 4));
            #pragma unroll
            for (int jh = 0; jh < 2; jh++) {
                int j = jj * 2 + jh;
                uint32_t bH[2] = { bh[2*jh], bh[2*jh+1] };
                mma_bf16(acc[0][j], aH[0], bH);
                mma_bf16(acc[1][j], aH[1], bH);
            }
        }
        if (c < 31) {
            float vx[8] = {px0.x,px0.y,px0.z,px0.w,px1.x,px1.y,px1.z,px1.w};
            uint32_t xh[4];
            #pragma unroll
            for (int w = 0; w < 4; w++) {
                float a0 = vx[2*w], a1 = vx[2*w+1];
                xh[w] = bfpack(a0, a1);
                rowsq += a0*a0 + a1*a1;
            }
            int so = lm * WROW + half * 4;
            *(uint4*)(dynsm + (0+nxt)*STW + so) = make_uint4(xh[0],xh[1],xh[2],xh[3]);
            *(uint4*)(dynsm + (2+nxt)*STW + so) = peH;
        }
        __syncthreads();
    }

    // per-row ||x||^2 -> inv_x
    sRow[lm][half] = rowsq;
    __syncthreads();
    if (tid < 128) {
        float n2 = sRow[tid][0] + sRow[tid][1];
        sN2[tid]  = n2;
        sInv[tid] = 1.0f / fmaxf(sqrtf(n2), EPSN);
    }
    __syncthreads();

    // argmin pass 1: score = esq - 2*inv_x*dot (bf16-approx)
    #pragma unroll
    for (int s = 0; s < 2; s++) {
        #pragma unroll
        for (int rh = 0; rh < 2; rh++) {
            int row = m0 + s*16 + g + rh*8;
            float inv2 = 2.0f * sInv[row];
            float bv = FLT_MAX;
            int   bi = 1 << 30;
            #pragma unroll
            for (int j = 0; j < 8; j++) {
                #pragma unroll
                for (int cc = 0; cc < 2; cc++) {
                    int col = n0 + 8*j + 2*tig + cc;
                    float sc = fmaf(-inv2, acc[s][j][rh*2 + cc], sEsq[col]);
                    if (sc < bv || (sc == bv && col < bi)) { bv = sc; bi = col; }
                }
            }
            #pragma unroll
            for (int o = 2; o > 0; o >>= 1) {
                float ov = __shfl_down_sync(0xffffffffu, bv, o, 4);
                int   oi = __shfl_down_sync(0xffffffffu, bi, o, 4);
                if (ov < bv || (ov == bv && oi < bi)) { bv = ov; bi = oi; }
            }
            if (tig == 0) { sval[nw][row] = bv; sidx[nw][row] = bi; }
        }
    }
    __syncthreads();

    if (tid < 128) {
        float v0 = sval[0][tid], v1 = sval[1][tid];
        int   i0 = sidx[0][tid], i1 = sidx[1][tid];
        if (v1 < v0 || (v1 == v0 && i1 < i0)) { scol[tid] = i1; sSc[tid] = v1; }
        else                                  { scol[tid] = i0; sSc[tid] = v0; }
    }
    __syncthreads();

    // pass 2: collect candidates within MARGIN of row-min
    #pragma unroll
    for (int s = 0; s < 2; s++) {
        #pragma unroll
        for (int rh = 0; rh < 2; rh++) {
            int row = m0 + s*16 + g + rh*8;
            float inv2 = 2.0f * sInv[row];
            float thresh = sSc[row] + MARGIN;
            int   win = scol[row];
            #pragma unroll
            for (int j = 0; j < 8; j++) {
                #pragma unroll
                for (int cc = 0; cc < 2; cc++) {
                    int col = n0 + 8*j + 2*tig + cc;
                    float sc = fmaf(-inv2, acc[s][j][rh*2 + cc], sEsq[col]);
                    if (sc <= thresh && col != win) {
                        int p = atomicAdd(&cand_cnt[row], 1);
                        if (p < 7) cand_col[row][p] = col;
                    }
                }
            }
        }
    }
    __syncthreads();

    // rescore close rows exactly in fp32 (warp per row)
    const float* ebase = emb + (size_t)t * NPER * D;
    for (int r = wid; r < rows; r += 8) {
        int nc = cand_cnt[r];
        if (nc == 0) continue;
        int tok = toks[r];
        const float4* xp = (const float4*)(x + (size_t)tok * D);
        float4 xa = xp[lane], xb = xp[lane + 32], xc = xp[lane + 64], xd = xp[lane + 96];
        float inv2 = 2.0f * sInv[r];
        float bv = FLT_MAX;
        int   bi = 1 << 30;
        int total = (nc > 7) ? NPER : (nc + 1);
        for (int q = 0; q < total; q++) {
            int col;
            if (nc > 7) col = q;
            else        col = (q == 0) ? scol[r] : cand_col[r][q - 1];
            const float4* ep = (const float4*)(ebase + (size_t)col * D);
            float4 ea = ep[lane], eb = ep[lane + 32], ec = ep[lane + 64], ed = ep[lane + 96];
            float d = xa.x*ea.x + xa.y*ea.y + xa.z*ea.z + xa.w*ea.w
                    + xb.x*eb.x + xb.y*eb.y + xb.z*eb.z + xb.w*eb.w
                    + xc.x*ec.x + xc.y*ec.y + xc.z*ec.z + xc.w*ec.w
                    + xd.x*ed.x + xd.y*ed.y + xd.z*ed.z + xd.w*ed.w;
            #pragma unroll
            for (int o = 16; o > 0; o >>= 1) d += __shfl_xor_sync(0xffffffffu, d, o);
            float sc = fmaf(-inv2, d, sEsq[col]);
            if (sc < bv || (sc == bv && col < bi)) { bv = sc; bi = col; }
        }
        if (lane == 0) { scol[r] = bi; sSc[r] = bv; }
    }
    __syncthreads();

    // idx write + analytic loss
    float lacc = 0.f;
    if (tid < 128 && tid < rows) {
        int col = scol[tid];
        out_idx[toks[tid]] = (float)(t * NPER + col);
        float esqw = sEsq[col];
        float inve = 1.0f / fmaxf(sqrtf(esqw), EPSN);
        lacc = esqw*inve*inve + sN2[tid]*sInv[tid]*sInv[tid] - (esqw - sSc[tid])*inve;
    }
    #pragma unroll
    for (int o = 16; o > 0; o >>= 1) lacc += __shfl_down_sync(0xffffffffu, lacc, o);
    if (tid < 128 && lane == 0) lsum[wid] = lacc;
    __syncthreads();
    if (tid == 0)
        atomicAdd(&g_loss, lsum[0] + lsum[1] + lsum[2] + lsum[3]);

    // write quantized rows (straight-through forward value == normalized code)
    for (int r = wid; r < rows; r += 8) {
        int tok = toks[r];
        int col = scol[r];
        float inve = 1.0f / fmaxf(sqrtf(sEsq[col]), EPSN);
        const float4* ep = (const float4*)(ebase + (size_t)col * D);
        float4* op = (float4*)(out + (size_t)tok * D);
        #pragma unroll
        for (int q = 0; q < 4; q++) {
            float4 e = ep[lane + q*32];
            op[lane + q*32] = make_float4(e.x*inve, e.y*inve, e.z*inve, e.w*inve);
        }
    }
}

// ---------------- uniform loss: 2 rows per block (full SM coverage) -----------
__global__ __launch_bounds__(256) void k_usim(const int* __restrict__ sampled, int S,
                                              float* __restrict__ out, int N) {
    int i0 = blockIdx.x * 2;
    int R = min(2, S - i0);
    __shared__ float si[2][D];
    __shared__ int   slab[2];
    __shared__ float wsum[8][2], wpos[8][2];

    int tid = threadIdx.x, lane = tid & 31, wid = tid >> 5;
    for (int r = 0; r < R; r++)
        ((float2*)si[r])[tid] = ((const float2*)(g_se + (size_t)(i0 + r) * D))[tid];
    if (tid < R) slab[tid] = sampled[i0 + tid] / NPER;
    __syncthreads();

    float sum0 = 0.f, pos0 = 0.f, sum1 = 0.f, pos1 = 0.f;

    const float4* b0p = (const float4*)si[0];
    const float4* b1p = (const float4*)si[1];
    float4 b00 = b0p[lane],      b01 = b0p[lane + 32],
           b02 = b0p[lane + 64], b03 = b0p[lane + 96];
    float4 b10 = b1p[lane],      b11 = b1p[lane + 32],
           b12 = b1p[lane + 64], b13 = b1p[lane + 96];

    for (int j = wid; j < S; j += 8) {
        const float4* gj = (const float4*)(g_se + (size_t)j * D);
        float4 a0 = gj[lane], a1 = gj[lane + 32], a2 = gj[lane + 64], a3 = gj[lane + 96];
        int labj = sampled[j] / NPER;
        float d0 = a0.x*b00.x + a0.y*b00.y + a0.z*b00.z + a0.w*b00.w
                 + a1.x*b01.x + a1.y*b01.y + a1.z*b01.z + a1.w*b01.w
                 + a2.x*b02.x + a2.y*b02.y + a2.z*b02.z + a2.w*b02.w
                 + a3.x*b03.x + a3.y*b03.y + a3.z*b03.z + a3.w*b03.w;
        float d1 = a0.x*b10.x + a0.y*b10.y + a0.z*b10.z + a0.w*b10.w
                 + a1.x*b11.x + a1.y*b11.y + a1.z*b11.z + a1.w*b11.w
                 + a2.x*b12.x + a2.y*b12.y + a2.z*b12.z + a2.w*b12.w
                 + a3.x*b13.x + a3.y*b13.y + a3.z*b13.z + a3.w*b13.w;
        #pragma unroll
        for (int o = 16; o > 0; o >>= 1) {
            d0 += __shfl_down_sync(0xffffffffu, d0, o);
            d1 += __shfl_down_sync(0xffffffffu, d1, o);
        }
        if (lane == 0) {
            if (j != i0) {
                float e = expf(d0 / TEMP);
                sum0 += e;
                if (labj == slab[0]) pos0 += e;
            }
            if (j != i0 + 1) {
                float e = expf(d1 / TEMP);
                sum1 += e;
                if (labj == slab[1]) pos1 += e;
            }
        }
    }
    if (lane == 0) {
        wsum[wid][0] = sum0; wpos[wid][0] = pos0;
        wsum[wid][1] = sum1; wpos[wid][1] = pos1;
    }
    __syncthreads();
    if (tid < R) {
        float ts = 0.f, tp = 0.f;
        #pragma unroll
        for (int w = 0; w < 8; w++) { ts += wsum[w][tid]; tp += wpos[w][tid]; }
        atomicAdd(&g_usum, -logf(tp / ts));
    }
    __threadfence();
    __syncthreads();
    if (tid == 0) {
        int old = atomicAdd(&g_done, 1);
        if (old == gridDim.x - 1) {
            g_done = 0;
            size_t ND = (size_t)N * D;
            out[ND]     = 1.25f * g_loss / (float)((size_t)N * D);
            out[ND + 1] = g_usum / (float)S;
        }
    }
}

// ---------------- launcher ----------------
extern "C" void kernel_launch(void* const* d_in, const int* in_sizes, int n_in,
                              void* d_out, int out_size) {
    const float* x       = (const float*)d_in[0];
    const int*   Q       = (const int*)d_in[1];
    const float* emb     = (const float*)d_in[2];
    const int*   sampled = (const int*)d_in[3];
    float* out = (float*)d_out;

    int N = in_sizes[0] / D;
    int S = in_sizes[3];
    size_t ND = (size_t)N * D;
    float* out_idx = out + ND + 2;

    cudaFuncSetAttribute(k_gemm_fused, cudaFuncAttributeMaxDynamicSharedMemorySize,
                         4 * STW * 4);

    k_prep<<<NCODES + HB + S, 128>>>(emb, Q, N, sampled, S);
    k_scatter<<<(N + 255) / 256, 256>>>(Q, N);
    dim3 gg(MAXTILES, NTYPES);
    k_gemm_fused<<<gg, 256, 4 * STW * 4>>>(x, emb, out, out_idx);
    k_usim<<<(S + 1) / 2, 256>>>(sampled, S, out, N);
}